// round 7
// baseline (speedup 1.0000x reference)
#include <cuda_runtime.h>
#include <cstdint>

// PoolingNms: MaxPool2d(k=3, stride=3) + MaxUnpool2d fused.
// x: [16, 1, 1536, 1536] fp32. Keep only the first-argmax element of each
// non-overlapping 3x3 block; zero elsewhere.
//
// R7: exploit output sparsity (8/9 zeros). Phase 1 stages the input tile into
// smem (coalesced v8, L2::evict_last) and simultaneously streams v8 zeros over
// the output tile. Phase 2 does the per-block argmax from smem (conflict-free
// LDS.128, 48B lane stride) and scatters ONLY the 4 maxima per thread straight
// to gmem (barrier orders zeros before scatters; addresses disjoint across
// threads). This removes the entire output reconstruct round-trip through
// smem (144KB -> 72KB crossbar traffic per tile) that made L1 the bottleneck
// (75.9%) in R6.

static constexpr int W  = 1536;
static constexpr int H  = 1536;
static constexpr int BC = 16;                    // batch * channels
static constexpr int TROWS = 6;                  // rows per tile
static constexpr int TILE_FLOATS = TROWS * W;    // 9216 floats = 36KB
static constexpr int TILE_VEC8   = TILE_FLOATS / 8;   // 1152
static constexpr int NTHREADS = 288;
static constexpr int V8_PER_THREAD = TILE_VEC8 / NTHREADS;   // 4
static constexpr int TILES_PER_IMAGE = H / TROWS;            // 256

__device__ __forceinline__ void ldg_v8_evict_last(const float* p, uint32_t r[8]) {
    asm("ld.global.L2::evict_last.v8.b32 {%0,%1,%2,%3,%4,%5,%6,%7}, [%8];"
        : "=r"(r[0]), "=r"(r[1]), "=r"(r[2]), "=r"(r[3]),
          "=r"(r[4]), "=r"(r[5]), "=r"(r[6]), "=r"(r[7])
        : "l"(p));
}

__device__ __forceinline__ void stg_v8_zero(float* p) {
    asm volatile("st.global.v8.b32 [%0], {%1,%1,%1,%1,%1,%1,%1,%1};"
                 :: "l"(p), "r"(0u) : "memory");
}

__global__ __launch_bounds__(NTHREADS)
void pooling_nms_kernel(const float* __restrict__ x, float* __restrict__ out) {
    __shared__ __align__(32) float tile[TILE_FLOATS];

    const int tid = threadIdx.x;
    const int b   = blockIdx.x;
    const int bc  = b >> 8;                 // b / TILES_PER_IMAGE
    const int tr  = b & (TILES_PER_IMAGE - 1);

    const size_t base = ((size_t)bc * H + (size_t)tr * TROWS) * W;
    const float* __restrict__ src = x + base;
    float* __restrict__ dst       = out + base;

    // Phase 1: stage input tile into smem + stream zeros over the output tile.
    #pragma unroll
    for (int j = 0; j < V8_PER_THREAD; j++) {
        int i = tid + NTHREADS * j;         // 0..1151
        uint32_t r[8];
        ldg_v8_evict_last(src + (size_t)i * 8, r);
        uint4* sv = reinterpret_cast<uint4*>(tile + (size_t)i * 8);
        sv[0] = make_uint4(r[0], r[1], r[2], r[3]);
        sv[1] = make_uint4(r[4], r[5], r[6], r[7]);
        stg_v8_zero(dst + (size_t)i * 8);
    }
    __syncthreads();   // orders this CTA's zero-stores before its scatters

    // Phase 2: 256 threads own one 3x12 patch (4 pool blocks) each.
    if (tid < 256) {
        const int g  = tid >> 7;            // row-group within tile (0..1)
        const int pw = tid & 127;           // patch column (0..127)
        const float* rp = tile + g * 3 * W + pw * 12;

        float best[4];
        int   ofs[4];                       // dr*W + col within patch

        #pragma unroll
        for (int dr = 0; dr < 3; dr++) {
            // 3 conflict-free LDS.128 per row (48B lane stride).
            float4 a = *reinterpret_cast<const float4*>(rp + dr * W);
            float4 q = *reinterpret_cast<const float4*>(rp + dr * W + 4);
            float4 c = *reinterpret_cast<const float4*>(rp + dr * W + 8);
            float v[12] = {a.x, a.y, a.z, a.w, q.x, q.y, q.z, q.w,
                           c.x, c.y, c.z, c.w};
            #pragma unroll
            for (int col = 0; col < 12; col++) {
                const int blk = col / 3;
                const int o   = dr * W + col;
                if (dr == 0 && (col % 3) == 0) {
                    best[blk] = v[col]; ofs[blk] = o;
                } else if (v[col] > best[blk]) {   // strict >: first max wins
                    best[blk] = v[col]; ofs[blk] = o;
                }
            }
        }

        // Scatter the 4 maxima (disjoint addresses across all threads).
        float* dp = dst + g * 3 * W + pw * 12;
        #pragma unroll
        for (int blk = 0; blk < 4; blk++) {
            dp[ofs[blk]] = best[blk];
        }
    }
}

extern "C" void kernel_launch(void* const* d_in, const int* in_sizes, int n_in,
                              void* d_out, int out_size) {
    const float* x = (const float*)d_in[0];
    float* out = (float*)d_out;
    pooling_nms_kernel<<<BC * TILES_PER_IMAGE, NTHREADS>>>(x, out);
}